// round 16
// baseline (speedup 1.0000x reference)
#include <cuda_runtime.h>

#define NTH   1024      // threads per block
#define NMAX  128       // n <= 100
#define MMAX  320       // m <= 300
#define NCW   ((MMAX + 31) / 32)   // column bitmask words
#define ECAP  2048      // shared-memory CSR capacity
#define MAXE  30720     // >= n*m worst case
#define FULLMASK 0xffffffffu
#define IINF  0x7fffffff
#define RMEMPTY 0xffffffffffffffffULL

// device globals (no allocation allowed); zero-initialized at load and
// restored each run by the solver block (replay-safe).
__device__ int                g_ne = 0;
__device__ int                g_done = 0;
__device__ int                g_deg[NMAX];
__device__ unsigned int       g_colbits[NCW];
__device__ unsigned long long g_rowmin[NMAX];   // packed (wq_biased<<16)|j
__device__ unsigned long long g_epk[MAXE];
__device__ short              g_ccol[MAXE];   // fallback CSR (E > ECAP)
__device__ int                g_cwq[MAXE];

// g_rowmin starts zero-initialized; treat 0 as "unset" is wrong, so producers
// initialize implicitly: rows with deg==0 are never read (rowlist excludes
// them) BUT zero would corrupt rows with edges. Hence solver resets to
// RMEMPTY after each run, and the very first run needs RMEMPTY too: we get
// that by having producers use atomicMin against RMEMPTY... zero-init breaks
// this. Fix: producers write atomicMin(key ^ flip)? Simplest correct scheme:
// store BIAS-key = key + 1 so 0 is "smaller than everything" never happens.
// Instead: producers atomicMin on (key), solver treats rowmin as valid ONLY
// for rows with deg>0, and we XOR-flip: store ~key and use atomicMax.
// ~RMEMPTY = 0 == zero-init == identity for atomicMax. Decode: key = ~stored.

// Quantize w = C + 0.5 (C = -iou, iou fp32 in (0.5,1]) at scale 2^24.
// Both fp32 ops are EXACT (w is a multiple of 2^-24, |w| < 0.5), so the
// whole solver runs in exact integer arithmetic. wq in [-2^23, -1].
__device__ __forceinline__ int quantw(float cw) {
    return __float2int_rn(__fmul_rn(__fadd_rn(cw, 0.5f), 16777216.0f));
}

// Fused kernel: IoU blocks emit packed quantized edges + row-degree +
// column-bitmask + per-row argmin metadata; one dedicated solver block
// pre-initializes, waits, compacts (edge + rowmin LDGs prefetched across
// the barrier), scatters CSR, then runs greedy JV init (decoded from
// producer rowmins) + exact integer SSP min-cost matching (label-in-slot
// frontier Dijkstra with speculative steering prefetch) with aggregated
// dummy sink (provably equivalent to lap.lapjv(C, cost_limit=-0.5,
// extend_cost=True) restricted to real pairs; optimum unique a.s., so
// tie-break order is immaterial).
__global__ void __launch_bounds__(NTH, 1)
matcher_kernel(const float* __restrict__ tgt, const float* __restrict__ prp,
               int n, int m, float* __restrict__ out) {
    __shared__ short cs_col[ECAP];
    __shared__ int   cs_wq[ECAP];
    __shared__ int   cs_off[NMAX + 1];
    __shared__ int   cur_off[NMAX];
    __shared__ unsigned long long s_rm[NMAX];
    __shared__ short colmap[MMAX], cinv[MMAX];
    __shared__ short rowlist[NMAX], bestcol[NMAX];
    __shared__ int   rc4i[MMAX];      // greedy column-claim (atomicMin)
    __shared__ int   u[NMAX], v[MMAX];
    __shared__ short path[MMAX], row4col[MMAX];
    __shared__ short col4row[NMAX];
    __shared__ unsigned char SC[MMAX];
    __shared__ short pos[MMAX];       // column -> frontier slot (-1 if none)
    __shared__ int   frlab[MMAX];     // frontier labels (by slot)
    __shared__ short frcol[MMAX];     // frontier columns (by slot)
    __shared__ short srl[NMAX];       // scanned rows, in order
    __shared__ short scl[MMAX];       // selected columns, in order
    __shared__ int   scv[MMAX];       // labels at selection time
    __shared__ int   s_frn;
    __shared__ int s_nr, s_mp;

    const int tid = threadIdx.x;
    const int nio = (int)gridDim.x - 1;          // # IoU blocks

    if ((int)blockIdx.x < nio) {
        // ---- IoU block: exact fp32 IoU for this slice (1 pair/thread) ----
        const int nm = n * m;
        int idx = blockIdx.x * NTH + tid;
        bool wrote = false;
        if (idx < nm) {
            int i = idx / m, j = idx - i * m;
            float4 a = __ldg((const float4*)(tgt) + i);   // [x0,y0,x1,y1]
            float4 b = __ldg((const float4*)(prp) + j);

            // round-to-nearest intrinsics block FMA contraction: exact ref bits
            float area_a = __fmul_rn(__fsub_rn(a.z, a.x), __fsub_rn(a.w, a.y));
            float area_b = __fmul_rn(__fsub_rn(b.z, b.x), __fsub_rn(b.w, b.y));
            float ltx = fmaxf(a.x, b.x), lty = fmaxf(a.y, b.y);
            float rbx = fminf(a.z, b.z), rby = fminf(a.w, b.w);
            float wx = fmaxf(__fsub_rn(rbx, ltx), 0.0f);
            float wy = fmaxf(__fsub_rn(rby, lty), 0.0f);
            float inter = __fmul_rn(wx, wy);
            float uni = __fsub_rn(__fadd_rn(area_a, area_b), inter);
            float iou = __fdiv_rn(inter, uni);

            // only IoU>0.5 pairs can appear in the padded lapjv optimum
            if (iou > 0.5f) {
                int wq = quantw(-iou);   // exact int weight, in [-2^23,-1]
                unsigned rij = (unsigned)((i << 16) | j);
                unsigned long long key =
                    ((unsigned long long)(unsigned)(wq + 8388608) << 32) | rij;
                int p = atomicAdd(&g_ne, 1);        // p < n*m <= MAXE always
                g_epk[p] = key;
                atomicAdd(&g_deg[i], 1);
                atomicOr(&g_colbits[j >> 5], 1u << (j & 31));
                // per-row argmin of (wq, j), lexicographic, via atomicMax of
                // the COMPLEMENT (zero-init == identity for max)
                unsigned long long rkey =
                    ((unsigned long long)(unsigned)(wq + 8388608) << 16)
                    | (unsigned)j;
                atomicMax(&g_rowmin[i], ~rkey);
                wrote = true;
            }
        }
        if (wrote) __threadfence();            // publish this thread's writes
        __syncthreads();                       // order all fences before bump
        if (tid == 0) atomicAdd(&g_done, 1);
        return;
    }

    // =========== dedicated solver block ===========
    // pre-initialize edge-independent state (overlaps with IoU blocks)
    for (int x = tid; x < m; x += NTH) {
        rc4i[x] = IINF;
        v[x] = 0;
        SC[x] = 0;
        pos[x] = -1;
    }
    for (int x = tid; x < n + m; x += NTH) out[x] = -1.0f;  // defaults
    __syncthreads();

    // wait for all IoU blocks (single wave: 31 blocks << #SMs, no deadlock)
    if (tid == 0) {
        volatile int* vd = &g_done;
        while (*vd != nio) { }
    }
    __syncthreads();
    __threadfence();                       // acquire all blocks' writes

    const int E = g_ne;                    // exact (<= n*m <= MAXE)
    const bool small = (E <= ECAP);

    // speculative preloads: issue LDGs NOW so latency hides behind the
    // compaction below (neither load depends on it)
    unsigned long long mykey = 0;
    const bool have = (tid < E);
    if (have) mykey = g_epk[tid];
    if (tid < n) s_rm[tid] = ~g_rowmin[tid];   // decode complement

    // ---- compaction from producer metadata:
    //      warp 0 = column bitmask, warp 1 = row degrees + CSR offsets ----
    if (tid < 32) {
        int ncw = (m + 31) / 32;
        unsigned w = (tid < ncw) ? g_colbits[tid] : 0u;   // one LDG, full MLP
        int cnt = __popc(w);
        int incl = cnt;
        #pragma unroll
        for (int off = 1; off < 32; off <<= 1) {
            int t = __shfl_up_sync(FULLMASK, incl, off);
            if (tid >= off) incl += t;
        }
        int base = incl - cnt;                 // exclusive prefix
        unsigned ww = w;
        int p = base;
        while (ww) {
            int bpos = __ffs(ww) - 1; ww &= ww - 1;
            int j = tid * 32 + bpos;
            cinv[j] = (short)p; colmap[p] = (short)j; p++;
        }
        if (tid == 31) s_mp = incl;            // total active columns
    } else if (tid < 64) {
        int lane = tid - 32;
        int nch = (n + 31) / 32;               // <= 4 chunks
        int dv[4];
        #pragma unroll
        for (int c = 0; c < 4; ++c) {          // independent LDGs (MLP)
            int i = c * 32 + lane;
            dv[c] = (c < nch && i < n) ? g_deg[i] : 0;
        }
        int rbase = 0, obase = 0;
        #pragma unroll
        for (int c = 0; c < 4; ++c) {
            if (c >= nch) break;
            int i = c * 32 + lane;
            int d = dv[c];
            bool f = d > 0;
            unsigned mask = __ballot_sync(FULLMASK, f);
            int rpos = rbase + __popc(mask & ((1u << lane) - 1));
            if (f) rowlist[rpos] = (short)i;
            rbase += __popc(mask);
            int incl = d;
            #pragma unroll
            for (int off = 1; off < 32; off <<= 1) {
                int t = __shfl_up_sync(FULLMASK, incl, off);
                if (lane >= off) incl += t;
            }
            int excl = obase + incl - d;
            if (i < n) { cs_off[i] = excl; cur_off[i] = excl; }
            obase += __shfl_sync(FULLMASK, incl, 31);
        }
        if (lane == 0) { s_nr = rbase; cs_off[n] = obase; }
    }
    __syncthreads();
    const int mp = s_mp, nr = s_nr;

    // ---- CSR scatter: preloaded key first, rare overflow via loop ----
    if (small) {
        if (have) {
            int wq = (int)(mykey >> 32) - 8388608;
            unsigned ij = (unsigned)mykey;
            int i = ij >> 16, j = ij & 0xffff;
            int p = atomicAdd(&cur_off[i], 1);
            cs_col[p] = cinv[j]; cs_wq[p] = wq;
        }
        for (int e = NTH + tid; e < E; e += NTH) {
            unsigned long long key = g_epk[e];
            int wq = (int)(key >> 32) - 8388608;
            unsigned ij = (unsigned)key;
            int i = ij >> 16, j = ij & 0xffff;
            int p = atomicAdd(&cur_off[i], 1);
            cs_col[p] = cinv[j]; cs_wq[p] = wq;
        }
    } else {
        for (int e = tid; e < E; e += NTH) {
            unsigned long long key = (e == tid) ? mykey : g_epk[e];
            int wq = (int)(key >> 32) - 8388608;
            unsigned ij = (unsigned)key;
            int i = ij >> 16, j = ij & 0xffff;
            int p = atomicAdd(&cur_off[i], 1);
            g_ccol[p] = cinv[j]; g_cwq[p] = wq;
        }
    }
    __syncthreads();

    // warps >= 1 reset globals for the next replay WHILE warp 0 solves
    if (tid >= 32) {
        int t = tid - 32;
        const int RTH = NTH - 32;
        for (int x = t; x < n; x += RTH) { g_deg[x] = 0; g_rowmin[x] = 0ULL; }
        for (int x = t; x < NCW; x += RTH) g_colbits[x] = 0;
        if (t == 0) { g_ne = 0; g_done = 0; }
    }

    // ---- exact integer SSP min-cost matching (warp 0) ----
    if (tid < 32) {
        const short* Ccol = small ? cs_col : g_ccol;
        const int*   Cwq  = small ? cs_wq  : g_cwq;

        // greedy JV init from producer rowmins: u[i] = min_j w_ij (feasible:
        // wq <= -1 so dummy reduced cost -u[i] >= 0); bestcol = lowest-j
        // argmin (identical to scanning — cinv is monotone). Parallel column
        // claim via atomicMin: lowest row index wins.
        for (int rr = tid; rr < nr; rr += 32) {
            int io = rowlist[rr];
            unsigned long long key = s_rm[io];
            int bw = (int)(key >> 16) - 8388608;
            int bj = cinv[(int)(key & 0xffff)];
            u[rr] = bw;
            bestcol[rr] = (short)bj;
            atomicMin(&rc4i[bj], rr);
        }
        __syncwarp();
        for (int rr = tid; rr < nr; rr += 32) {
            int j = bestcol[rr];
            col4row[rr] = (rc4i[j] == rr) ? (short)j : (short)-1;
        }
        for (int x = tid; x < mp; x += 32) {
            int r = rc4i[x];
            row4col[x] = (r == IINF) ? (short)-1 : (short)r;
        }
        __syncwarp();

        for (int rr = 0; rr < nr; ++rr) {
            if (col4row[rr] >= 0) continue;   // satisfied by greedy init

            if (tid == 0) s_frn = 0;
            __syncwarp();

            int i = rr;
            int shortest = 0;
            int spcD = IINF;                // aggregated dummy sink label
            int dpred = -1;
            int nsr = 0;                    // # scanned rows
            int sink = -1;
            int minVal = 0;
            bool dummySink = false;

            while (true) {
                if (tid == 0) srl[nsr] = (short)i;
                const int ui = u[i];

                // dummy ("stay unmatched") relax: w=0, v_dummy=0
                int dc = shortest - ui;
                if (dc < spcD) { spcD = dc; dpred = i; }

                // relax this row's edges; labels live IN the frontier slots
                int io = rowlist[i];
                int b = cs_off[io], e2 = cs_off[io + 1];
                int base = shortest - ui;
                for (int e = b + tid; e < e2; e += 32) {
                    int j = Ccol[e];
                    if (!SC[j]) {
                        int red = base + Cwq[e] - v[j];
                        int p = pos[j];
                        if (p < 0) {
                            p = atomicAdd(&s_frn, 1);
                            frlab[p] = red; frcol[p] = (short)j;
                            pos[j] = (short)p;
                            path[j] = (short)i;
                        } else if (red < frlab[p]) {
                            frlab[p] = red;
                            path[j] = (short)i;
                        }
                    }
                }
                __syncwarp();
                int frn = s_frn;

                // per-lane argmin over frontier labels (selected hold IINF)
                int best = IINF; int bslot = -1;
                for (int t = tid; t < frn; t += 32) {
                    int s = frlab[t];
                    if (s < best) { best = s; bslot = t; }
                }
                // speculative steering prefetch for the LANE-LOCAL best
                // (frcol append-only; row4col constant within one Dijkstra)
                int bcol = (bslot >= 0) ? (int)frcol[bslot] : 0;
                int br4  = (bslot >= 0) ? (int)row4col[bcol] : -1;

                int gmin = __reduce_min_sync(FULLMASK, best);
                if (spcD < gmin) { dummySink = true; minVal = spcD; nsr++; break; }
                unsigned who = __ballot_sync(FULLMASK, best == gmin);
                int src = __ffs(who) - 1;
                int bidx  = __shfl_sync(FULLMASK, bcol, src);
                int r4    = __shfl_sync(FULLMASK, br4, src);
                int bslw  = __shfl_sync(FULLMASK, bslot, src);
                minVal = gmin;

                // record selection; mark scanned (all lanes write same values)
                SC[bidx] = 1;
                frlab[bslw] = IINF;          // excluded from future argmins
                scl[nsr] = (short)bidx;
                scv[nsr] = gmin;
                nsr++;
                if (r4 < 0) { sink = bidx; break; }
                i = r4;
                shortest = gmin;
            }
            __syncwarp();

            // O(steps) dual updates (JV form; dummy edges stay feasible)
            for (int t = tid; t < nsr; t += 32) {
                int ii = srl[t];
                u[ii] += (t == 0) ? minVal : (minVal - scv[t - 1]);
            }
            int nsc = nsr - 1;               // selected columns (sink incl.)
            for (int t = tid; t < nsc; t += 32)
                v[scl[t]] -= minVal - scv[t];

            // frontier cleanup: reset pos/SC only for touched columns
            int frn = s_frn;
            for (int t = tid; t < frn; t += 32) {
                int j = frcol[t];
                pos[j] = -1; SC[j] = 0;
            }
            __syncwarp();

            // augment (lane 0, integer-only)
            if (tid == 0) {
                if (dummySink) {
                    int ii = dpred;
                    if (ii != rr) {
                        int j = col4row[ii];
                        col4row[ii] = -1;       // ii becomes unmatched
                        while (true) {
                            int i2 = path[j];
                            row4col[j] = (short)i2;
                            int nxt = col4row[i2];
                            col4row[i2] = (short)j;
                            j = nxt;
                            if (i2 == rr) break;
                        }
                    }
                } else {
                    int j = sink;
                    while (true) {
                        int i2 = path[j];
                        row4col[j] = (short)i2;
                        int nxt = col4row[i2];
                        col4row[i2] = (short)j;
                        j = nxt;
                        if (i2 == rr) break;
                    }
                }
            }
            __syncwarp();
        }
    }
    __syncthreads();

    // ---- matched outputs (defaults written above) ----
    for (int r = tid; r < nr; r += NTH) {
        int j = col4row[r];
        if (j >= 0) {
            int oi = rowlist[r], oj = colmap[j];
            out[oi] = (float)oj;
            out[n + oj] = (float)oi;
        }
    }
}

extern "C" void kernel_launch(void* const* d_in, const int* in_sizes, int n_in,
                              void* d_out, int out_size) {
    const float* tgt = (const float*)d_in[0];   // target_bbox   [N,4] fp32
    const float* prp = (const float*)d_in[1];   // proposal_bbox [M,4] fp32
    int N = in_sizes[0] / 4;
    int M = in_sizes[1] / 4;
    int nm = N * M;
    int blocks = (nm + NTH - 1) / NTH + 1;      // +1 dedicated solver block
    matcher_kernel<<<blocks, NTH>>>(tgt, prp, N, M, (float*)d_out);
}

// round 17
// speedup vs baseline: 1.0234x; 1.0234x over previous
#include <cuda_runtime.h>

#define NTH   1024      // threads per block
#define NMAX  128       // n <= 100
#define MMAX  320       // m <= 300
#define NCW   ((MMAX + 31) / 32)   // column bitmask words
#define ECAP  2048      // shared-memory CSR capacity
#define MAXE  30720     // >= n*m worst case
#define FULLMASK 0xffffffffu
#define IINF  0x7fffffff

// device globals (no allocation allowed); zero-initialized at load and
// re-zeroed each run by the solver block (replay-safe).
__device__ int                g_ne = 0;
__device__ int                g_done = 0;
__device__ int                g_deg[NMAX];
__device__ unsigned int       g_colbits[NCW];
__device__ unsigned long long g_epk[MAXE];
__device__ short              g_ccol[MAXE];   // fallback CSR (E > ECAP)
__device__ int                g_cwq[MAXE];

// Quantize w = C + 0.5 (C = -iou, iou fp32 in (0.5,1]) at scale 2^24.
// Both fp32 ops are EXACT (w is a multiple of 2^-24, |w| < 0.5), so the
// whole solver runs in exact integer arithmetic. wq in [-2^23, -1].
__device__ __forceinline__ int quantw(float cw) {
    return __float2int_rn(__fmul_rn(__fadd_rn(cw, 0.5f), 16777216.0f));
}

// Fused kernel: IoU blocks emit packed quantized edges + row-degree +
// column-bitmask metadata; one dedicated solver block pre-initializes,
// waits, compacts (edge LDGs prefetched across the barrier), scatters CSR,
// then runs greedy JV init + exact integer SSP min-cost matching
// (label-in-slot frontier Dijkstra with speculative steering prefetch)
// with aggregated dummy sink (provably equivalent to lap.lapjv(C,
// cost_limit=-0.5, extend_cost=True) restricted to real pairs; optimum
// unique a.s., so tie-break order is immaterial).
__global__ void __launch_bounds__(NTH, 1)
matcher_kernel(const float* __restrict__ tgt, const float* __restrict__ prp,
               int n, int m, float* __restrict__ out) {
    __shared__ short cs_col[ECAP];
    __shared__ int   cs_wq[ECAP];
    __shared__ int   cs_off[NMAX + 1];
    __shared__ int   cur_off[NMAX];
    __shared__ short colmap[MMAX], cinv[MMAX];
    __shared__ short rowlist[NMAX], bestcol[NMAX];
    __shared__ int   rc4i[MMAX];      // greedy column-claim (atomicMin)
    __shared__ int   u[NMAX], v[MMAX];
    __shared__ short path[MMAX], row4col[MMAX];
    __shared__ short col4row[NMAX];
    __shared__ unsigned char SC[MMAX];
    __shared__ short pos[MMAX];       // column -> frontier slot (-1 if none)
    __shared__ int   frlab[MMAX];     // frontier labels (by slot)
    __shared__ short frcol[MMAX];     // frontier columns (by slot)
    __shared__ short srl[NMAX];       // scanned rows, in order
    __shared__ short scl[MMAX];       // selected columns, in order
    __shared__ int   scv[MMAX];       // labels at selection time
    __shared__ int   s_frn;
    __shared__ int s_nr, s_mp;

    const int tid = threadIdx.x;
    const int nio = (int)gridDim.x - 1;          // # IoU blocks

    if ((int)blockIdx.x < nio) {
        // ---- IoU block: exact fp32 IoU for this slice (1 pair/thread) ----
        const int nm = n * m;
        int idx = blockIdx.x * NTH + tid;
        bool wrote = false;
        if (idx < nm) {
            int i = idx / m, j = idx - i * m;
            float4 a = __ldg((const float4*)(tgt) + i);   // [x0,y0,x1,y1]
            float4 b = __ldg((const float4*)(prp) + j);

            // round-to-nearest intrinsics block FMA contraction: exact ref bits
            float area_a = __fmul_rn(__fsub_rn(a.z, a.x), __fsub_rn(a.w, a.y));
            float area_b = __fmul_rn(__fsub_rn(b.z, b.x), __fsub_rn(b.w, b.y));
            float ltx = fmaxf(a.x, b.x), lty = fmaxf(a.y, b.y);
            float rbx = fminf(a.z, b.z), rby = fminf(a.w, b.w);
            float wx = fmaxf(__fsub_rn(rbx, ltx), 0.0f);
            float wy = fmaxf(__fsub_rn(rby, lty), 0.0f);
            float inter = __fmul_rn(wx, wy);
            float uni = __fsub_rn(__fadd_rn(area_a, area_b), inter);
            float iou = __fdiv_rn(inter, uni);

            // only IoU>0.5 pairs can appear in the padded lapjv optimum
            if (iou > 0.5f) {
                int wq = quantw(-iou);   // exact int weight, in [-2^23,-1]
                unsigned long long key =
                    ((unsigned long long)(unsigned)(wq + 8388608) << 32)
                    | (unsigned)((i << 16) | j);
                int p = atomicAdd(&g_ne, 1);        // p < n*m <= MAXE always
                g_epk[p] = key;
                atomicAdd(&g_deg[i], 1);
                atomicOr(&g_colbits[j >> 5], 1u << (j & 31));
                wrote = true;
            }
        }
        if (wrote) __threadfence();            // publish this thread's writes
        __syncthreads();                       // order all fences before bump
        if (tid == 0) atomicAdd(&g_done, 1);
        return;
    }

    // =========== dedicated solver block ===========
    // pre-initialize edge-independent state (overlaps with IoU blocks)
    for (int x = tid; x < m; x += NTH) {
        rc4i[x] = IINF;
        v[x] = 0;
        SC[x] = 0;
        pos[x] = -1;
    }
    for (int x = tid; x < n + m; x += NTH) out[x] = -1.0f;  // defaults
    __syncthreads();

    // wait for all IoU blocks (single wave: 31 blocks << #SMs, no deadlock)
    if (tid == 0) {
        volatile int* vd = &g_done;
        while (*vd != nio) { }
    }
    __syncthreads();
    __threadfence();                       // acquire all blocks' writes

    const int E = g_ne;                    // exact (<= n*m <= MAXE)
    const bool small = (E <= ECAP);

    // speculative edge preload: issue the LDG NOW so its latency hides
    // behind the compaction below (the load doesn't depend on it)
    unsigned long long mykey = 0;
    const bool have = (tid < E);
    if (have) mykey = g_epk[tid];

    // ---- compaction from producer metadata:
    //      warp 0 = column bitmask, warp 1 = row degrees + CSR offsets ----
    if (tid < 32) {
        int ncw = (m + 31) / 32;
        unsigned w = (tid < ncw) ? g_colbits[tid] : 0u;   // one LDG, full MLP
        int cnt = __popc(w);
        int incl = cnt;
        #pragma unroll
        for (int off = 1; off < 32; off <<= 1) {
            int t = __shfl_up_sync(FULLMASK, incl, off);
            if (tid >= off) incl += t;
        }
        int base = incl - cnt;                 // exclusive prefix
        unsigned ww = w;
        int p = base;
        while (ww) {
            int bpos = __ffs(ww) - 1; ww &= ww - 1;
            int j = tid * 32 + bpos;
            cinv[j] = (short)p; colmap[p] = (short)j; p++;
        }
        if (tid == 31) s_mp = incl;            // total active columns
    } else if (tid < 64) {
        int lane = tid - 32;
        int nch = (n + 31) / 32;               // <= 4 chunks
        int dv[4];
        #pragma unroll
        for (int c = 0; c < 4; ++c) {          // independent LDGs (MLP)
            int i = c * 32 + lane;
            dv[c] = (c < nch && i < n) ? g_deg[i] : 0;
        }
        int rbase = 0, obase = 0;
        #pragma unroll
        for (int c = 0; c < 4; ++c) {
            if (c >= nch) break;
            int i = c * 32 + lane;
            int d = dv[c];
            bool f = d > 0;
            unsigned mask = __ballot_sync(FULLMASK, f);
            int rpos = rbase + __popc(mask & ((1u << lane) - 1));
            if (f) rowlist[rpos] = (short)i;
            rbase += __popc(mask);
            int incl = d;
            #pragma unroll
            for (int off = 1; off < 32; off <<= 1) {
                int t = __shfl_up_sync(FULLMASK, incl, off);
                if (lane >= off) incl += t;
            }
            int excl = obase + incl - d;
            if (i < n) { cs_off[i] = excl; cur_off[i] = excl; }
            obase += __shfl_sync(FULLMASK, incl, 31);
        }
        if (lane == 0) { s_nr = rbase; cs_off[n] = obase; }
    }
    __syncthreads();
    const int mp = s_mp, nr = s_nr;

    // ---- CSR scatter: preloaded key first, rare overflow via loop ----
    if (small) {
        if (have) {
            int wq = (int)(mykey >> 32) - 8388608;
            unsigned ij = (unsigned)mykey;
            int i = ij >> 16, j = ij & 0xffff;
            int p = atomicAdd(&cur_off[i], 1);
            cs_col[p] = cinv[j]; cs_wq[p] = wq;
        }
        for (int e = NTH + tid; e < E; e += NTH) {
            unsigned long long key = g_epk[e];
            int wq = (int)(key >> 32) - 8388608;
            unsigned ij = (unsigned)key;
            int i = ij >> 16, j = ij & 0xffff;
            int p = atomicAdd(&cur_off[i], 1);
            cs_col[p] = cinv[j]; cs_wq[p] = wq;
        }
    } else {
        for (int e = tid; e < E; e += NTH) {
            unsigned long long key = (e == tid) ? mykey : g_epk[e];
            int wq = (int)(key >> 32) - 8388608;
            unsigned ij = (unsigned)key;
            int i = ij >> 16, j = ij & 0xffff;
            int p = atomicAdd(&cur_off[i], 1);
            g_ccol[p] = cinv[j]; g_cwq[p] = wq;
        }
    }
    __syncthreads();

    // warps >= 1 reset globals for the next replay WHILE warp 0 solves,
    // then exit (no final block barrier; warp 0 writes all outputs)
    if (tid >= 32) {
        int t = tid - 32;
        const int RTH = NTH - 32;
        for (int x = t; x < n; x += RTH) g_deg[x] = 0;
        for (int x = t; x < NCW; x += RTH) g_colbits[x] = 0;
        if (t == 0) { g_ne = 0; g_done = 0; }
        return;
    }

    // ---- exact integer SSP min-cost matching (warp 0) ----
    {
        const short* Ccol = small ? cs_col : g_ccol;
        const int*   Cwq  = small ? cs_wq  : g_cwq;

        // greedy JV init: u[i] = min_j w_ij (feasible: wq <= -1 so dummy
        // reduced cost -u[i] >= 0). Parallel column claim via atomicMin:
        // lowest row index wins.
        for (int rr = tid; rr < nr; rr += 32) {
            int io = rowlist[rr];
            int b = cs_off[io], e2 = cs_off[io + 1];
            int bw = IINF; int bj = 0x7fff;
            for (int e = b; e < e2; ++e) {
                int w = Cwq[e]; int j = Ccol[e];
                if (w < bw || (w == bw && j < bj)) { bw = w; bj = j; }
            }
            u[rr] = bw;
            bestcol[rr] = (short)bj;
            atomicMin(&rc4i[bj], rr);
        }
        __syncwarp();
        int myfree = 0;
        for (int rr = tid; rr < nr; rr += 32) {
            int j = bestcol[rr];
            bool won = (rc4i[j] == rr);
            col4row[rr] = won ? (short)j : (short)-1;
            if (!won) myfree++;
        }
        for (int x = tid; x < mp; x += 32) {
            int r = rc4i[x];
            row4col[x] = (r == IINF) ? (short)-1 : (short)r;
        }
        // count of rows needing an augmenting path (for early loop exit)
        #pragma unroll
        for (int off = 16; off; off >>= 1)
            myfree += __shfl_xor_sync(FULLMASK, myfree, off);
        int nfree = myfree;
        __syncwarp();

        for (int rr = 0; rr < nr && nfree > 0; ++rr) {
            if (col4row[rr] >= 0) continue;   // satisfied by greedy init
            nfree--;

            if (tid == 0) s_frn = 0;
            __syncwarp();

            int i = rr;
            int shortest = 0;
            int spcD = IINF;                // aggregated dummy sink label
            int dpred = -1;
            int nsr = 0;                    // # scanned rows
            int sink = -1;
            int minVal = 0;
            bool dummySink = false;

            while (true) {
                if (tid == 0) srl[nsr] = (short)i;
                const int ui = u[i];

                // dummy ("stay unmatched") relax: w=0, v_dummy=0
                int dc = shortest - ui;
                if (dc < spcD) { spcD = dc; dpred = i; }

                // relax this row's edges; labels live IN the frontier slots
                int io = rowlist[i];
                int b = cs_off[io], e2 = cs_off[io + 1];
                int base = shortest - ui;
                for (int e = b + tid; e < e2; e += 32) {
                    int j = Ccol[e];
                    if (!SC[j]) {
                        int red = base + Cwq[e] - v[j];
                        int p = pos[j];
                        if (p < 0) {
                            p = atomicAdd(&s_frn, 1);
                            frlab[p] = red; frcol[p] = (short)j;
                            pos[j] = (short)p;
                            path[j] = (short)i;
                        } else if (red < frlab[p]) {
                            frlab[p] = red;
                            path[j] = (short)i;
                        }
                    }
                }
                __syncwarp();
                int frn = s_frn;

                // per-lane argmin over frontier labels (selected hold IINF)
                int best = IINF; int bslot = -1;
                for (int t = tid; t < frn; t += 32) {
                    int s = frlab[t];
                    if (s < best) { best = s; bslot = t; }
                }
                // speculative steering prefetch for the LANE-LOCAL best
                // (frcol append-only; row4col constant within one Dijkstra)
                int bcol = (bslot >= 0) ? (int)frcol[bslot] : 0;
                int br4  = (bslot >= 0) ? (int)row4col[bcol] : -1;

                int gmin = __reduce_min_sync(FULLMASK, best);
                if (spcD < gmin) { dummySink = true; minVal = spcD; nsr++; break; }
                unsigned who = __ballot_sync(FULLMASK, best == gmin);
                int src = __ffs(who) - 1;
                int bidx  = __shfl_sync(FULLMASK, bcol, src);
                int r4    = __shfl_sync(FULLMASK, br4, src);
                int bslw  = __shfl_sync(FULLMASK, bslot, src);
                minVal = gmin;

                // record selection; mark scanned (all lanes write same values)
                SC[bidx] = 1;
                frlab[bslw] = IINF;          // excluded from future argmins
                scl[nsr] = (short)bidx;
                scv[nsr] = gmin;
                nsr++;
                if (r4 < 0) { sink = bidx; break; }
                i = r4;
                shortest = gmin;
            }
            __syncwarp();

            // O(steps) dual updates (JV form; dummy edges stay feasible)
            for (int t = tid; t < nsr; t += 32) {
                int ii = srl[t];
                u[ii] += (t == 0) ? minVal : (minVal - scv[t - 1]);
            }
            int nsc = nsr - 1;               // selected columns (sink incl.)
            for (int t = tid; t < nsc; t += 32)
                v[scl[t]] -= minVal - scv[t];

            // frontier cleanup: reset pos/SC only for touched columns
            int frn = s_frn;
            for (int t = tid; t < frn; t += 32) {
                int j = frcol[t];
                pos[j] = -1; SC[j] = 0;
            }
            __syncwarp();

            // augment (lane 0, integer-only)
            if (tid == 0) {
                if (dummySink) {
                    int ii = dpred;
                    if (ii != rr) {
                        int j = col4row[ii];
                        col4row[ii] = -1;       // ii becomes unmatched
                        while (true) {
                            int i2 = path[j];
                            row4col[j] = (short)i2;
                            int nxt = col4row[i2];
                            col4row[i2] = (short)j;
                            j = nxt;
                            if (i2 == rr) break;
                        }
                    }
                } else {
                    int j = sink;
                    while (true) {
                        int i2 = path[j];
                        row4col[j] = (short)i2;
                        int nxt = col4row[i2];
                        col4row[i2] = (short)j;
                        j = nxt;
                        if (i2 == rr) break;
                    }
                }
            }
            __syncwarp();
        }

        // ---- matched outputs by warp 0 (defaults written pre-solve) ----
        for (int r = tid; r < nr; r += 32) {
            int j = col4row[r];
            if (j >= 0) {
                int oi = rowlist[r], oj = colmap[j];
                out[oi] = (float)oj;
                out[n + oj] = (float)oi;
            }
        }
    }
}

extern "C" void kernel_launch(void* const* d_in, const int* in_sizes, int n_in,
                              void* d_out, int out_size) {
    const float* tgt = (const float*)d_in[0];   // target_bbox   [N,4] fp32
    const float* prp = (const float*)d_in[1];   // proposal_bbox [M,4] fp32
    int N = in_sizes[0] / 4;
    int M = in_sizes[1] / 4;
    int nm = N * M;
    int blocks = (nm + NTH - 1) / NTH + 1;      // +1 dedicated solver block
    matcher_kernel<<<blocks, NTH>>>(tgt, prp, N, M, (float*)d_out);
}